// round 16
// baseline (speedup 1.0000x reference)
#include <cuda_runtime.h>
#include <cuda_fp16.h>
#include <math.h>
#include <stdint.h>

// Problem constants
#define T_   8
#define N_   20000
#define C_   128
#define E_   320000
#define H_   4
#define DH_  32
#define WIN_ 4
#define K_   5
#define CH_  512
#define TN_  (T_ * N_)
#define TNC_ ((long)T_ * N_ * C_)

// ---------------------------------------------------------------------------
// Scratch (__device__ globals; no cudaMalloc allowed)
// ---------------------------------------------------------------------------
__device__ float g_inv[N_];
__device__ int   g_cnt[N_];
__device__ int   g_off[N_ + 1];
__device__ int   g_cur[N_];
__device__ int   g_srcs[E_];
__device__ float g_spare[TN_];
__device__ __half g_Xh[T_ * N_ * C_];   // x fp16 -> x1 fp16 -> attout (staged reuse)
__device__ __half g_B1h[T_ * N_ * C_];  // gather outputs
__device__ __half g_X2h[T_ * N_ * C_];  // x2 fp16 (Q GEMM A + FFN resid)
__device__ __half g_Gh[T_ * N_ * C_];   // gated x2 (gather2 in)
__device__ __half g_QKVh[3 * T_ * N_ * C_];
__device__ __half g_B2h[T_ * N_ * C_];  // aggregated fp16 (feeds LIF)
__device__ __half g_Fh[T_ * N_ * C_];   // ffn_in fp16
// transposed fp16 weights: Ws,Wq,Wk,Wv,Wo (128x128), f1 (512x128), f2 (128x512)
__device__ __half g_WTh[5 * 128 * 128 + 512 * 128 + 128 * 512];

// ---------------------------------------------------------------------------
// Helpers
// ---------------------------------------------------------------------------
__device__ __forceinline__ uint32_t smem_u32(const void* p) {
    uint32_t a;
    asm("{ .reg .u64 t; cvta.to.shared.u64 t, %1; cvt.u32.u64 %0, t; }" : "=r"(a) : "l"(p));
    return a;
}
__device__ __forceinline__ float warp_sum(float v) {
#pragma unroll
    for (int o = 16; o; o >>= 1) v += __shfl_xor_sync(0xffffffffu, v, o);
    return v;
}
__device__ __forceinline__ float gelu_t(float v) {
    float t = 0.7978845608028654f * (v + 0.044715f * v * v * v);
    float th; asm("tanh.approx.f32 %0, %1;" : "=f"(th) : "f"(t));
    return 0.5f * v * (1.0f + th);
}
__device__ __forceinline__ void cp16(uint32_t dst, const void* src) {
    asm volatile("cp.async.cg.shared.global [%0], [%1], 16;" :: "r"(dst), "l"(src));
}
#define CP_COMMIT() asm volatile("cp.async.commit_group;" ::: "memory")
#define CP_WAIT0()  asm volatile("cp.async.wait_group 0;" ::: "memory")
#define CP_WAIT1()  asm volatile("cp.async.wait_group 1;" ::: "memory")

__device__ __forceinline__ void mma_f16(float* c, const uint32_t* a, uint32_t b0, uint32_t b1) {
    asm volatile("mma.sync.aligned.m16n8k16.row.col.f32.f16.f16.f32 "
                 "{%0,%1,%2,%3}, {%4,%5,%6,%7}, {%8,%9}, {%0,%1,%2,%3};"
                 : "+f"(c[0]), "+f"(c[1]), "+f"(c[2]), "+f"(c[3])
                 : "r"(a[0]), "r"(a[1]), "r"(a[2]), "r"(a[3]), "r"(b0), "r"(b1));
}
__device__ __forceinline__ uint32_t ldu32(const __half* p) {
    return *(const uint32_t*)p;
}

// ---------------------------------------------------------------------------
// Merged prep kernel: weight transposes + fp16 x copy + degree histogram.
// ---------------------------------------------------------------------------
__device__ __forceinline__ void tcvt_tile(const float* __restrict__ in,
                                          __half* __restrict__ out, int Kd, int Ncol,
                                          int bx, int by) {
    __shared__ float tile[32][33];
    int kb = by * 32, nb = bx * 32;
    int tx = threadIdx.x & 31, ty = threadIdx.x >> 5;
#pragma unroll
    for (int j = 0; j < 32; j += 8)
        tile[ty + j][tx] = in[(long)(kb + ty + j) * Ncol + nb + tx];
    __syncthreads();
#pragma unroll
    for (int j = 0; j < 32; j += 8) {
        float v = tile[tx][ty + j];
        out[(long)(nb + ty + j) * Kd + kb + tx] = __float2half(v);
    }
}

#define PREP_SQ   80
#define PREP_F1   (PREP_SQ + 64)
#define PREP_F2   (PREP_F1 + 64)
#define PREP_F2H  (PREP_F2 + 20000)
#define PREP_END  (PREP_F2H + 1250)

__global__ void k_prep(const float* w0, const float* w1, const float* w2,
                       const float* w3, const float* w4,
                       const float* f1w, const float* f2w,
                       __half* WTh,
                       const float* __restrict__ x, __half* __restrict__ xh,
                       const int* __restrict__ ei, int* __restrict__ cnt) {
    int b = blockIdx.x;
    if (b < PREP_SQ) {
        int w = b >> 4, tile = b & 15;
        const float* in;
        switch (w) {
            case 0: in = w0; break;
            case 1: in = w1; break;
            case 2: in = w2; break;
            case 3: in = w3; break;
            default: in = w4; break;
        }
        tcvt_tile(in, WTh + (long)w * 16384, 128, 128, tile & 3, tile >> 2);
    } else if (b < PREP_F1) {
        int t = b - PREP_SQ;
        tcvt_tile(f1w, WTh + 81920, 128, 512, t & 15, t >> 4);
    } else if (b < PREP_F2) {
        int t = b - PREP_F1;
        tcvt_tile(f2w, WTh + 147456, 512, 128, t & 3, t >> 2);
    } else if (b < PREP_F2H) {
        long i = ((long)(b - PREP_F2) * 256 + threadIdx.x) * 4;
        float4 v = *(const float4*)(x + i);
        __half2 h0 = __floats2half2_rn(v.x, v.y);
        __half2 h1 = __floats2half2_rn(v.z, v.w);
        uint2 u;
        u.x = *(uint32_t*)&h0;
        u.y = *(uint32_t*)&h1;
        *(uint2*)(xh + i) = u;
    } else {
        int e = (b - PREP_F2H) * 256 + threadIdx.x;
        if (e < E_) atomicAdd(&cnt[ei[E_ + e]], 1);
    }
}

// ---------------------------------------------------------------------------
// CSR scan + fill
// ---------------------------------------------------------------------------
__global__ void k_scan(const int* __restrict__ cnt, int* __restrict__ off,
                       int* __restrict__ cur, float* __restrict__ inv) {
    __shared__ int wsum[32];
    __shared__ int sbase;
    __shared__ int stot;
    if (threadIdx.x == 0) sbase = 0;
    __syncthreads();
    int lane = threadIdx.x & 31, w = threadIdx.x >> 5;
    for (int start = 0; start < N_; start += 1024) {
        int i = start + threadIdx.x;
        int v = (i < N_) ? cnt[i] : 0;
        int s = v;
#pragma unroll
        for (int o = 1; o < 32; o <<= 1) {
            int tmp = __shfl_up_sync(0xffffffffu, s, o);
            if (lane >= o) s += tmp;
        }
        if (lane == 31) wsum[w] = s;
        __syncthreads();
        if (w == 0) {
            int ws = wsum[lane];
#pragma unroll
            for (int o = 1; o < 32; o <<= 1) {
                int tmp = __shfl_up_sync(0xffffffffu, ws, o);
                if (lane >= o) ws += tmp;
            }
            wsum[lane] = ws;
            if (lane == 31) stot = ws;
        }
        __syncthreads();
        int incl = s + (w > 0 ? wsum[w - 1] : 0) + sbase;
        if (i < N_) {
            int excl = incl - v;
            off[i] = excl;
            cur[i] = excl;
            inv[i] = 1.0f / fmaxf((float)v, 1.0f);
        }
        __syncthreads();
        if (threadIdx.x == 0) sbase += stot;
        __syncthreads();
    }
    if (threadIdx.x == 0) off[N_] = sbase;
}

__global__ void k_fill(const int* __restrict__ ei, int* __restrict__ cur,
                       int* __restrict__ srcs) {
    int e = blockIdx.x * blockDim.x + threadIdx.x;
    if (e >= E_) return;
    int d = ei[E_ + e];
    int idx = atomicAdd(&cur[d], 1);
    srcs[idx] = ei[e];
}

// ---------------------------------------------------------------------------
// fp16 gather-mean, 4 warps per node (timestep pair each), LDG.128.
// Warp qq covers t in {2qq, 2qq+1} via lane parity; lane = 1 timestep x 8 ch.
// 4-edge unroll: 4 independent LDG.128 in flight per lane per iteration.
// ---------------------------------------------------------------------------
__global__ void k_gather_h(const __half* __restrict__ xin, const int* __restrict__ off,
                           const int* __restrict__ srcs, const float* __restrict__ inv,
                           __half* __restrict__ out) {
    int gw = (int)((blockIdx.x * blockDim.x + threadIdx.x) >> 5);
    int lane = threadIdx.x & 31;
    if (gw >= 4 * N_) return;
    int n  = gw >> 2;
    int qq = gw & 3;                 // timestep pair: t in {2qq, 2qq+1}
    const int p = lane >> 4;         // parity -> t = 2qq + p
    const int c = lane & 15;         // 16B chunk (8 halfs)
    int s0 = off[n], s1 = off[n + 1];
    float acc[8];
#pragma unroll
    for (int q = 0; q < 8; q++) acc[q] = 0.0f;

    const __half* xb = xin + c * 8 + (long)(2 * qq + p) * N_ * C_;

    int j = s0;
    for (; j + 3 < s1; j += 4) {
        int sA = srcs[j];
        int sB = srcs[j + 1];
        int sC = srcs[j + 2];
        int sD = srcs[j + 3];
        uint4 uA = *(const uint4*)(xb + (long)sA * C_);
        uint4 uB = *(const uint4*)(xb + (long)sB * C_);
        uint4 uC = *(const uint4*)(xb + (long)sC * C_);
        uint4 uD = *(const uint4*)(xb + (long)sD * C_);
        const __half2* ha = (const __half2*)&uA;
        const __half2* hb = (const __half2*)&uB;
        const __half2* hc = (const __half2*)&uC;
        const __half2* hd = (const __half2*)&uD;
#pragma unroll
        for (int q = 0; q < 4; q++) {
            float2 fa = __half22float2(ha[q]);
            float2 fb = __half22float2(hb[q]);
            float2 fc = __half22float2(hc[q]);
            float2 fd = __half22float2(hd[q]);
            acc[2 * q + 0] += (fa.x + fb.x) + (fc.x + fd.x);
            acc[2 * q + 1] += (fa.y + fb.y) + (fc.y + fd.y);
        }
    }
    for (; j < s1; j++) {
        int s = srcs[j];
        uint4 u = *(const uint4*)(xb + (long)s * C_);
        const __half2* hu = (const __half2*)&u;
#pragma unroll
        for (int q = 0; q < 4; q++) {
            float2 f = __half22float2(hu[q]);
            acc[2 * q + 0] += f.x;
            acc[2 * q + 1] += f.y;
        }
    }
    float iv = inv[n];
    __half2 o[4];
#pragma unroll
    for (int q = 0; q < 4; q++)
        o[q] = __floats2half2_rn(acc[2 * q + 0] * iv, acc[2 * q + 1] * iv);
    *(uint4*)(out + ((long)(2 * qq + p) * N_ + n) * C_ + c * 8) = *(uint4*)o;
}

// ---------------------------------------------------------------------------
// GEMM core macros (pipelined, BK=32, 2-stage)
// ---------------------------------------------------------------------------
#define LDA_  40
#define SA0   0
#define SA1   10240
#define SB0   20480
#define SB1   30720
#define SBIAS 40960
#define SG    41472
#define SBB   41984
#define SRED  42496
#define SMEM_GEMM (SRED + 2048)

// ---------------------------------------------------------------------------
// fp16 mma.sync GEMM: Out = epilogue( (A @ BT^T) + bias )
// EPI 0: bias; EPI 2: bias + fp32 residual + LayerNorm. OUTH: half output.
// ---------------------------------------------------------------------------
template <int EPI, bool OUTH>
__global__ __launch_bounds__(256)
void k_gemm_mma(const __half* __restrict__ A, const __half* __restrict__ BT,
                const float* __restrict__ bias, void* __restrict__ OutV,
                int Kd,
                const float* __restrict__ resid,
                const float* __restrict__ lng, const float* __restrict__ lnb) {
    extern __shared__ char smem[];
    uint32_t sbase = smem_u32(smem);
    const int tid = threadIdx.x;
    const int wid = tid >> 5, lane = tid & 31;
    const int g = lane >> 2, t = lane & 3;
    const int warp_m = wid & 3, warp_n = wid >> 2;
    const long m0 = (long)blockIdx.y * 128;

    float* sbias = (float*)(smem + SBIAS);
    float* sg    = (float*)(smem + SG);
    float* sbb   = (float*)(smem + SBB);
    float* sred1 = (float*)(smem + SRED);
    float* sred2 = (float*)(smem + SRED + 1024);

    if (tid < 128) {
        sbias[tid] = bias[tid];
        if (EPI == 2) { sg[tid] = lng[tid]; sbb[tid] = lnb[tid]; }
    }

    float c[2][8][4];
#pragma unroll
    for (int mt = 0; mt < 2; mt++)
#pragma unroll
        for (int nt = 0; nt < 8; nt++)
#pragma unroll
            for (int j = 0; j < 4; j++) c[mt][nt][j] = 0.0f;

    const int nck = Kd >> 5;
    const int srow = tid >> 2;
    const int sseg = (tid & 3) * 8;
    {
        uint32_t sa = sbase + SA0, sb = sbase + SB0;
#pragma unroll
        for (int i = 0; i < 2; i++) {
            int r = srow + 64 * i;
            cp16(sa + (uint32_t)(r * LDA_ + sseg) * 2, A  + (m0 + r) * Kd + sseg);
            cp16(sb + (uint32_t)(r * LDA_ + sseg) * 2, BT + (long)r * Kd + sseg);
        }
        CP_COMMIT();
    }

    for (int ck = 0; ck < nck; ck++) {
        if (ck + 1 < nck) {
            int buf = (ck + 1) & 1;
            uint32_t sa = sbase + (buf ? SA1 : SA0);
            uint32_t sb = sbase + (buf ? SB1 : SB0);
            long kb = (long)(ck + 1) * 32;
#pragma unroll
            for (int i = 0; i < 2; i++) {
                int r = srow + 64 * i;
                cp16(sa + (uint32_t)(r * LDA_ + sseg) * 2, A  + (m0 + r) * Kd + kb + sseg);
                cp16(sb + (uint32_t)(r * LDA_ + sseg) * 2, BT + (long)r * Kd + kb + sseg);
            }
            CP_COMMIT();
            CP_WAIT1();
        } else {
            CP_WAIT0();
        }
        __syncthreads();

        const __half* As = (const __half*)(smem + ((ck & 1) ? SA1 : SA0));
        const __half* Bs = (const __half*)(smem + ((ck & 1) ? SB1 : SB0));
#pragma unroll
        for (int ks = 0; ks < 2; ks++) {
            int k0 = ks * 16 + 2 * t;
            uint32_t a[2][4];
#pragma unroll
            for (int mt = 0; mt < 2; mt++) {
                const __half* ap = As + (warp_m * 32 + mt * 16 + g) * LDA_ + k0;
                a[mt][0] = ldu32(ap);
                a[mt][1] = ldu32(ap + 8 * LDA_);
                a[mt][2] = ldu32(ap + 8);
                a[mt][3] = ldu32(ap + 8 * LDA_ + 8);
            }
#pragma unroll
            for (int nt = 0; nt < 8; nt++) {
                const __half* bp = Bs + (warp_n * 64 + nt * 8 + g) * LDA_ + k0;
                uint32_t b0 = ldu32(bp);
                uint32_t b1 = ldu32(bp + 8);
#pragma unroll
                for (int mt = 0; mt < 2; mt++) mma_f16(c[mt][nt], a[mt], b0, b1);
            }
        }
        __syncthreads();
    }

    if (EPI == 2) {
#pragma unroll
        for (int mt = 0; mt < 2; mt++) {
#pragma unroll
            for (int h = 0; h < 2; h++) {
                int rib = warp_m * 32 + mt * 16 + h * 8 + g;
                long gr = m0 + rib;
                float s1 = 0.f, s2 = 0.f;
#pragma unroll
                for (int nt = 0; nt < 8; nt++) {
                    int col = warp_n * 64 + nt * 8 + 2 * t;
                    float2 rv = *(const float2*)(resid + gr * 128 + col);
                    float v0 = c[mt][nt][h * 2 + 0] + sbias[col]     + rv.x;
                    float v1 = c[mt][nt][h * 2 + 1] + sbias[col + 1] + rv.y;
                    c[mt][nt][h * 2 + 0] = v0;
                    c[mt][nt][h * 2 + 1] = v1;
                    s1 += v0 + v1;
                    s2 += v0 * v0 + v1 * v1;
                }
                s1 += __shfl_xor_sync(0xffffffffu, s1, 1);
                s1 += __shfl_xor_sync(0xffffffffu, s1, 2);
                s2 += __shfl_xor_sync(0xffffffffu, s2, 1);
                s2 += __shfl_xor_sync(0xffffffffu, s2, 2);
                if (t == 0) {
                    sred1[rib * 2 + warp_n] = s1;
                    sred2[rib * 2 + warp_n] = s2;
                }
            }
        }
        __syncthreads();
#pragma unroll
        for (int mt = 0; mt < 2; mt++) {
#pragma unroll
            for (int h = 0; h < 2; h++) {
                int rib = warp_m * 32 + mt * 16 + h * 8 + g;
                long gr = m0 + rib;
                float s1 = sred1[rib * 2] + sred1[rib * 2 + 1];
                float s2 = sred2[rib * 2] + sred2[rib * 2 + 1];
                float mu = s1 * (1.0f / 128.0f);
                float var = s2 * (1.0f / 128.0f) - mu * mu;
                float rs = rsqrtf(var + 1e-5f);
#pragma unroll
                for (int nt = 0; nt < 8; nt++) {
                    int col = warp_n * 64 + nt * 8 + 2 * t;
                    float o0 = (c[mt][nt][h * 2 + 0] - mu) * rs * sg[col]     + sbb[col];
                    float o1 = (c[mt][nt][h * 2 + 1] - mu) * rs * sg[col + 1] + sbb[col + 1];
                    if (OUTH) {
                        *(__half2*)((__half*)OutV + gr * 128 + col) = __floats2half2_rn(o0, o1);
                    } else {
                        *(float2*)((float*)OutV + gr * 128 + col) = make_float2(o0, o1);
                    }
                }
            }
        }
    } else {
#pragma unroll
        for (int mt = 0; mt < 2; mt++) {
#pragma unroll
            for (int h = 0; h < 2; h++) {
                long gr = m0 + warp_m * 32 + mt * 16 + h * 8 + g;
#pragma unroll
                for (int nt = 0; nt < 8; nt++) {
                    int col = warp_n * 64 + nt * 8 + 2 * t;
                    float v0 = c[mt][nt][h * 2 + 0] + sbias[col];
                    float v1 = c[mt][nt][h * 2 + 1] + sbias[col + 1];
                    if (OUTH) {
                        *(__half2*)((__half*)OutV + gr * 128 + col) = __floats2half2_rn(v0, v1);
                    } else {
                        *(float2*)((float*)OutV + gr * 128 + col) = make_float2(v0, v1);
                    }
                }
            }
        }
    }
}

// ---------------------------------------------------------------------------
// Fused QKV GEMM (pipelined): grid (3, 1250).
// ---------------------------------------------------------------------------
__global__ __launch_bounds__(256)
void k_gemm_qkv(const __half* __restrict__ Aq, const __half* __restrict__ Akv,
                const __half* __restrict__ WQKV,
                const float* __restrict__ bq, const float* __restrict__ bk,
                const float* __restrict__ bv, __half* __restrict__ QKV) {
    extern __shared__ char smem[];
    uint32_t sbase = smem_u32(smem);
    const int tid = threadIdx.x;
    const int wid = tid >> 5, lane = tid & 31;
    const int g = lane >> 2, t = lane & 3;
    const int warp_m = wid & 3, warp_n = wid >> 2;
    const long m0 = (long)blockIdx.y * 128;
    const int sel = blockIdx.x;

    const __half* A  = (sel == 0) ? Aq : Akv;
    const __half* BT = WQKV + (long)sel * 16384;
    const float* biasp = (sel == 0) ? bq : ((sel == 1) ? bk : bv);
    __half* Out = QKV + (long)sel * TNC_;

    float* sbias = (float*)(smem + SBIAS);
    if (tid < 128) sbias[tid] = biasp[tid];

    float c[2][8][4];
#pragma unroll
    for (int mt = 0; mt < 2; mt++)
#pragma unroll
        for (int nt = 0; nt < 8; nt++)
#pragma unroll
            for (int j = 0; j < 4; j++) c[mt][nt][j] = 0.0f;

    const int srow = tid >> 2;
    const int sseg = (tid & 3) * 8;
    {
        uint32_t sa = sbase + SA0, sb = sbase + SB0;
#pragma unroll
        for (int i = 0; i < 2; i++) {
            int r = srow + 64 * i;
            cp16(sa + (uint32_t)(r * LDA_ + sseg) * 2, A  + (m0 + r) * 128 + sseg);
            cp16(sb + (uint32_t)(r * LDA_ + sseg) * 2, BT + (long)r * 128 + sseg);
        }
        CP_COMMIT();
    }

#pragma unroll
    for (int ck = 0; ck < 4; ck++) {
        if (ck + 1 < 4) {
            int buf = (ck + 1) & 1;
            uint32_t sa = sbase + (buf ? SA1 : SA0);
            uint32_t sb = sbase + (buf ? SB1 : SB0);
            long kb = (long)(ck + 1) * 32;
#pragma unroll
            for (int i = 0; i < 2; i++) {
                int r = srow + 64 * i;
                cp16(sa + (uint32_t)(r * LDA_ + sseg) * 2, A  + (m0 + r) * 128 + kb + sseg);
                cp16(sb + (uint32_t)(r * LDA_ + sseg) * 2, BT + (long)r * 128 + kb + sseg);
            }
            CP_COMMIT();
            CP_WAIT1();
        } else {
            CP_WAIT0();
        }
        __syncthreads();

        const __half* As = (const __half*)(smem + ((ck & 1) ? SA1 : SA0));
        const __half* Bs = (const __half*)(smem + ((ck & 1) ? SB1 : SB0));
#pragma unroll
        for (int ks = 0; ks < 2; ks++) {
            int k0 = ks * 16 + 2 * t;
            uint32_t a[2][4];
#pragma unroll
            for (int mt = 0; mt < 2; mt++) {
                const __half* ap = As + (warp_m * 32 + mt * 16 + g) * LDA_ + k0;
                a[mt][0] = ldu32(ap);
                a[mt][1] = ldu32(ap + 8 * LDA_);
                a[mt][2] = ldu32(ap + 8);
                a[mt][3] = ldu32(ap + 8 * LDA_ + 8);
            }
#pragma unroll
            for (int nt = 0; nt < 8; nt++) {
                const __half* bp = Bs + (warp_n * 64 + nt * 8 + g) * LDA_ + k0;
                uint32_t b0 = ldu32(bp);
                uint32_t b1 = ldu32(bp + 8);
#pragma unroll
                for (int mt = 0; mt < 2; mt++) mma_f16(c[mt][nt], a[mt], b0, b1);
            }
        }
        __syncthreads();
    }

#pragma unroll
    for (int mt = 0; mt < 2; mt++) {
#pragma unroll
        for (int h = 0; h < 2; h++) {
            long gr = m0 + warp_m * 32 + mt * 16 + h * 8 + g;
#pragma unroll
            for (int nt = 0; nt < 8; nt++) {
                int col = warp_n * 64 + nt * 8 + 2 * t;
                float v0 = c[mt][nt][h * 2 + 0] + sbias[col];
                float v1 = c[mt][nt][h * 2 + 1] + sbias[col + 1];
                *(__half2*)(Out + gr * 128 + col) = __floats2half2_rn(v0, v1);
            }
        }
    }
}

// ---------------------------------------------------------------------------
// Fused FFN (fp16 operands): Out = LN( resid(fp16) + fc2(gelu(fc1(A))) )
// ---------------------------------------------------------------------------
#define FFS   136
#define FFTB  (128 * FFS * 2)
#define FFA   0
#define FFH   FFTB
#define FFW   (2 * FFTB)
#define FFBO  (3 * FFTB)
#define FFG   (FFBO + 512)
#define FFBB  (FFG + 512)
#define FFR1  (FFBB + 512)
#define FFR2  (FFR1 + 1024)
#define SMEM_FFN (FFR2 + 1024)

__global__ __launch_bounds__(256)
void k_ffn(const __half* __restrict__ A, const __half* __restrict__ F1T,
           const float* __restrict__ f1b, const __half* __restrict__ F2T,
           const float* __restrict__ f2b, const __half* __restrict__ residh,
           const float* __restrict__ lng, const float* __restrict__ lnb,
           float* __restrict__ Out) {
    extern __shared__ char smem[];
    uint32_t sbase = smem_u32(smem);
    __half* SA = (__half*)(smem + FFA);
    __half* SH = (__half*)(smem + FFH);
    __half* SW = (__half*)(smem + FFW);
    float* sbo = (float*)(smem + FFBO);
    float* sg  = (float*)(smem + FFG);
    float* sbb = (float*)(smem + FFBB);
    float* sred1 = (float*)(smem + FFR1);
    float* sred2 = (float*)(smem + FFR2);
    const int tid = threadIdx.x;
    const int wid = tid >> 5, lane = tid & 31;
    const int g = lane >> 2, t4 = lane & 3;
    const int wm = wid & 3, wn = wid >> 2;
    const long m0 = (long)blockIdx.x * 128;

    if (tid < 128) { sbo[tid] = f2b[tid]; sg[tid] = lng[tid]; sbb[tid] = lnb[tid]; }

    const int arow = tid >> 4;
    const int aseg = (tid & 15) * 8;
#pragma unroll
    for (int i = 0; i < 8; i++) {
        int r = arow + 16 * i;
        cp16(sbase + FFA + (uint32_t)(r * FFS + aseg) * 2, A + (m0 + r) * 128 + aseg);
    }
    CP_COMMIT();

    float oacc[2][8][4];
#pragma unroll
    for (int mt = 0; mt < 2; mt++)
#pragma unroll
        for (int nt = 0; nt < 8; nt++)
#pragma unroll
            for (int j = 0; j < 4; j++) oacc[mt][nt][j] = 0.0f;

    for (int ch = 0; ch < 4; ch++) {
#pragma unroll
        for (int i = 0; i < 8; i++) {
            int r = arow + 16 * i;
            cp16(sbase + FFW + (uint32_t)(r * FFS + aseg) * 2,
                 F1T + (long)(ch * 128 + r) * 128 + aseg);
        }
        CP_COMMIT();
        CP_WAIT0();
        __syncthreads();

        float hacc[2][8][4];
#pragma unroll
        for (int mt = 0; mt < 2; mt++)
#pragma unroll
            for (int nt = 0; nt < 8; nt++)
#pragma unroll
                for (int j = 0; j < 4; j++) hacc[mt][nt][j] = 0.0f;
#pragma unroll
        for (int ks = 0; ks < 8; ks++) {
            int k0 = ks * 16 + 2 * t4;
            uint32_t a[2][4];
#pragma unroll
            for (int mt = 0; mt < 2; mt++) {
                const __half* ap = SA + (wm * 32 + mt * 16 + g) * FFS + k0;
                a[mt][0] = ldu32(ap);
                a[mt][1] = ldu32(ap + 8 * FFS);
                a[mt][2] = ldu32(ap + 8);
                a[mt][3] = ldu32(ap + 8 * FFS + 8);
            }
#pragma unroll
            for (int nt = 0; nt < 8; nt++) {
                const __half* bp = SW + (wn * 64 + nt * 8 + g) * FFS + k0;
                uint32_t b0 = ldu32(bp);
                uint32_t b1 = ldu32(bp + 8);
#pragma unroll
                for (int mt = 0; mt < 2; mt++) mma_f16(hacc[mt][nt], a[mt], b0, b1);
            }
        }
        __syncthreads();

#pragma unroll
        for (int i = 0; i < 8; i++) {
            int r = arow + 16 * i;
            cp16(sbase + FFW + (uint32_t)(r * FFS + aseg) * 2,
                 F2T + (long)r * 512 + ch * 128 + aseg);
        }
        CP_COMMIT();

#pragma unroll
        for (int mt = 0; mt < 2; mt++) {
#pragma unroll
            for (int h = 0; h < 2; h++) {
                int row = wm * 32 + mt * 16 + h * 8 + g;
#pragma unroll
                for (int nt = 0; nt < 8; nt++) {
                    int col = wn * 64 + nt * 8 + 2 * t4;
                    float b0 = f1b[ch * 128 + col];
                    float b1 = f1b[ch * 128 + col + 1];
                    float h0 = gelu_t(hacc[mt][nt][h * 2 + 0] + b0);
                    float h1 = gelu_t(hacc[mt][nt][h * 2 + 1] + b1);
                    *(__half2*)(SH + row * FFS + col) = __floats2half2_rn(h0, h1);
                }
            }
        }
        CP_WAIT0();
        __syncthreads();

#pragma unroll
        for (int ks = 0; ks < 8; ks++) {
            int k0 = ks * 16 + 2 * t4;
            uint32_t a[2][4];
#pragma unroll
            for (int mt = 0; mt < 2; mt++) {
                const __half* ap = SH + (wm * 32 + mt * 16 + g) * FFS + k0;
                a[mt][0] = ldu32(ap);
                a[mt][1] = ldu32(ap + 8 * FFS);
                a[mt][2] = ldu32(ap + 8);
                a[mt][3] = ldu32(ap + 8 * FFS + 8);
            }
#pragma unroll
            for (int nt = 0; nt < 8; nt++) {
                const __half* bp = SW + (wn * 64 + nt * 8 + g) * FFS + k0;
                uint32_t b0 = ldu32(bp);
                uint32_t b1 = ldu32(bp + 8);
#pragma unroll
                for (int mt = 0; mt < 2; mt++) mma_f16(oacc[mt][nt], a[mt], b0, b1);
            }
        }
        __syncthreads();
    }

#pragma unroll
    for (int mt = 0; mt < 2; mt++) {
#pragma unroll
        for (int h = 0; h < 2; h++) {
            int rib = wm * 32 + mt * 16 + h * 8 + g;
            long gr = m0 + rib;
            float s1 = 0.f, s2 = 0.f;
#pragma unroll
            for (int nt = 0; nt < 8; nt++) {
                int col = wn * 64 + nt * 8 + 2 * t4;
                float2 rv = __half22float2(*(const __half2*)(residh + gr * 128 + col));
                float v0 = oacc[mt][nt][h * 2 + 0] + sbo[col]     + rv.x;
                float v1 = oacc[mt][nt][h * 2 + 1] + sbo[col + 1] + rv.y;
                oacc[mt][nt][h * 2 + 0] = v0;
                oacc[mt][nt][h * 2 + 1] = v1;
                s1 += v0 + v1;
                s2 += v0 * v0 + v1 * v1;
            }
            s1 += __shfl_xor_sync(0xffffffffu, s1, 1);
            s1 += __shfl_xor_sync(0xffffffffu, s1, 2);
            s2 += __shfl_xor_sync(0xffffffffu, s2, 1);
            s2 += __shfl_xor_sync(0xffffffffu, s2, 2);
            if (t4 == 0) {
                sred1[rib * 2 + wn] = s1;
                sred2[rib * 2 + wn] = s2;
            }
        }
    }
    __syncthreads();
#pragma unroll
    for (int mt = 0; mt < 2; mt++) {
#pragma unroll
        for (int h = 0; h < 2; h++) {
            int rib = wm * 32 + mt * 16 + h * 8 + g;
            long gr = m0 + rib;
            float s1 = sred1[rib * 2] + sred1[rib * 2 + 1];
            float s2 = sred2[rib * 2] + sred2[rib * 2 + 1];
            float mu = s1 * (1.0f / 128.0f);
            float var = s2 * (1.0f / 128.0f) - mu * mu;
            float rs = rsqrtf(var + 1e-5f);
#pragma unroll
            for (int nt = 0; nt < 8; nt++) {
                int col = wn * 64 + nt * 8 + 2 * t4;
                float o0 = (oacc[mt][nt][h * 2 + 0] - mu) * rs * sg[col]     + sbb[col];
                float o1 = (oacc[mt][nt][h * 2 + 1] - mu) * rs * sg[col + 1] + sbb[col + 1];
                *(float2*)(Out + gr * 128 + col) = make_float2(o0, o1);
            }
        }
    }
}

// ---------------------------------------------------------------------------
// x2 = LN(x1 + causal depthwise conv over time): warp-per-node, shuffle LN.
// ---------------------------------------------------------------------------
__global__ void k_conv_ln(const __half* __restrict__ x1h, const float* __restrict__ dk,
                          const float* __restrict__ g, const float* __restrict__ be,
                          const float* __restrict__ spikes,
                          __half* __restrict__ outh, __half* __restrict__ gh) {
    int n = (int)((blockIdx.x * blockDim.x + threadIdx.x) >> 5);
    int lane = threadIdx.x & 31;
    if (n >= N_) return;
    int c0 = lane * 4;
    float xs[T_][4];
#pragma unroll
    for (int t = 0; t < T_; t++) {
        uint2 u = *(const uint2*)(x1h + ((long)t * N_ + n) * C_ + c0);
        float2 f0 = __half22float2(*reinterpret_cast<__half2*>(&u.x));
        float2 f1 = __half22float2(*reinterpret_cast<__half2*>(&u.y));
        xs[t][0] = f0.x; xs[t][1] = f0.y; xs[t][2] = f1.x; xs[t][3] = f1.y;
    }
    float w[4][K_];
#pragma unroll
    for (int q = 0; q < 4; q++)
#pragma unroll
        for (int j = 0; j < K_; j++) w[q][j] = dk[(c0 + q) * K_ + j];
    float gc[4], bc[4];
#pragma unroll
    for (int q = 0; q < 4; q++) { gc[q] = g[c0 + q]; bc[q] = be[c0 + q]; }

#pragma unroll
    for (int t = 0; t < T_; t++) {
        float v[4];
#pragma unroll
        for (int q = 0; q < 4; q++) {
            float acc = xs[t][q];
#pragma unroll
            for (int j = 0; j < K_; j++)
                if (t - j >= 0) acc += w[q][j] * xs[t - j][q];
            v[q] = acc;
        }
        float l1 = v[0] + v[1] + v[2] + v[3];
        float l2 = v[0] * v[0] + v[1] * v[1] + v[2] * v[2] + v[3] * v[3];
        float s1 = warp_sum(l1);
        float s2 = warp_sum(l2);
        float mu = s1 * (1.0f / 128.0f);
        float var = s2 * (1.0f / 128.0f) - mu * mu;
        float rs = rsqrtf(var + 1e-5f);
        float spk = spikes[(long)t * N_ + n];
        float o[4];
#pragma unroll
        for (int q = 0; q < 4; q++) o[q] = (v[q] - mu) * rs * gc[q] + bc[q];
        __half2 h0 = __floats2half2_rn(o[0], o[1]);
        __half2 h1 = __floats2half2_rn(o[2], o[3]);
        uint2 uo;
        uo.x = *(uint32_t*)&h0;
        uo.y = *(uint32_t*)&h1;
        *(uint2*)(outh + ((long)t * N_ + n) * C_ + c0) = uo;
        __half2 g0 = __floats2half2_rn(o[0] * spk, o[1] * spk);
        __half2 g1 = __floats2half2_rn(o[2] * spk, o[3] * spk);
        uint2 ug;
        ug.x = *(uint32_t*)&g0;
        ug.y = *(uint32_t*)&g1;
        *(uint2*)(gh + ((long)t * N_ + n) * C_ + c0) = ug;
    }
}

// ---------------------------------------------------------------------------
// Windowed attention (fp16 I/O): 2 nodes per block, 8 warps (4 heads x 2).
// ---------------------------------------------------------------------------
__global__ void k_attn(const __half* __restrict__ q, const __half* __restrict__ k,
                       const __half* __restrict__ v, const int* __restrict__ tix,
                       __half* __restrict__ out) {
    int n = blockIdx.x * 2 + (threadIdx.x >> 7);
    int h = (threadIdx.x >> 5) & 3, d = threadIdx.x & 31;
    long base0 = (long)n * C_ + h * DH_ + d;
    float qv[T_], kv[T_], vv[T_];
    int ti[T_];
#pragma unroll
    for (int t = 0; t < T_; t++) {
        long idx = base0 + (long)t * N_ * C_;
        qv[t] = __half2float(q[idx]);
        kv[t] = __half2float(k[idx]);
        vv[t] = __half2float(v[idx]);
        ti[t] = tix[t];
    }
#pragma unroll
    for (int t = 0; t < T_; t++) {
        float sc[WIN_];
#pragma unroll
        for (int w = 0; w < WIN_; w++) {
            int tp = t - w; if (tp < 0) tp = 0;
            bool ok = (t >= w) && ((ti[t] - ti[tp]) < WIN_);
            float pr = (t >= w) ? qv[t] * kv[tp] : 0.0f;
            float dot = warp_sum(pr) * 0.17677669529663687f;
            sc[w] = ok ? dot : -1e9f;
        }
        float mx = sc[0];
#pragma unroll
        for (int w = 1; w < WIN_; w++) mx = fmaxf(mx, sc[w]);
        float den = 0.0f, ex[WIN_];
#pragma unroll
        for (int w = 0; w < WIN_; w++) { ex[w] = expf(sc[w] - mx); den += ex[w]; }
        float o = 0.0f;
#pragma unroll
        for (int w = 0; w < WIN_; w++)
            if (t - w >= 0) o += ex[w] * vv[t - w];
        out[base0 + (long)t * N_ * C_] = __float2half(o / den);
    }
}

// ---------------------------------------------------------------------------
// LIF scan + spike gate + channel-mean, block-per-node, ballot count.
// ---------------------------------------------------------------------------
__global__ void k_lif2(const __half* __restrict__ agg, __half* __restrict__ ffn_in,
                       float* __restrict__ outm) {
    int n = blockIdx.x;
    int c = threadIdx.x;
    int lane = c & 31, wi = c >> 5;
    __shared__ float red[T_][4];
    float a[T_];
#pragma unroll
    for (int t = 0; t < T_; t++)
        a[t] = __half2float(agg[((long)t * N_ + n) * C_ + c]);
    float vm = 0.0f;
#pragma unroll
    for (int t = 0; t < T_; t++) {
        float vn = 0.95f * vm + a[t];
        bool spk = (vn >= 1.0f);
        float s = spk ? 1.0f : 0.0f;
        vm = vn * (1.0f - s);
        ffn_in[((long)t * N_ + n) * C_ + c] = __float2half(a[t] * s);
        uint32_t bal = __ballot_sync(0xffffffffu, spk);
        if (lane == 0) red[t][wi] = (float)__popc(bal);
    }
    __syncthreads();
    if (c < T_)
        outm[(long)c * N_ + n] = (red[c][0] + red[c][1] + red[c][2] + red[c][3]) * (1.0f / 128.0f);
}

// ---------------------------------------------------------------------------
// Launch
// ---------------------------------------------------------------------------
extern "C" void kernel_launch(void* const* d_in, const int* in_sizes, int n_in,
                              void* d_out, int out_size) {
    const float* x      = (const float*)d_in[0];
    const float* spikes = (const float*)d_in[1];
    const int*   ei     = (const int*)d_in[2];
    const int*   tix    = (const int*)d_in[3];
    const float* Ws  = (const float*)d_in[4];
    const float* bs  = (const float*)d_in[5];
    const float* dk  = (const float*)d_in[6];
    const float* g1  = (const float*)d_in[7];
    const float* b1  = (const float*)d_in[8];
    const float* g2  = (const float*)d_in[9];
    const float* b2  = (const float*)d_in[10];
    const float* gf  = (const float*)d_in[11];
    const float* bf  = (const float*)d_in[12];
    const float* Wq  = (const float*)d_in[13];
    const float* bq  = (const float*)d_in[14];
    const float* Wk  = (const float*)d_in[15];
    const float* bk  = (const float*)d_in[16];
    const float* Wv  = (const float*)d_in[17];
    const float* bv  = (const float*)d_in[18];
    const float* Wo  = (const float*)d_in[19];
    const float* bo  = (const float*)d_in[20];
    const float* f1w = (const float*)d_in[21];
    const float* f1b = (const float*)d_in[22];
    const float* f2w = (const float*)d_in[23];
    const float* f2b = (const float*)d_in[24];

    float *inv, *spare;
    __half *Xh, *B1h, *X2h, *Gh, *QKVh, *B2h, *Fh, *WTh;
    int *cnt, *off, *cur, *srcs;
    cudaGetSymbolAddress((void**)&inv,  g_inv);
    cudaGetSymbolAddress((void**)&cnt,  g_cnt);
    cudaGetSymbolAddress((void**)&off,  g_off);
    cudaGetSymbolAddress((void**)&cur,  g_cur);
    cudaGetSymbolAddress((void**)&srcs, g_srcs);
    cudaGetSymbolAddress((void**)&spare, g_spare);
    cudaGetSymbolAddress((void**)&Xh,   g_Xh);
    cudaGetSymbolAddress((void**)&B1h,  g_B1h);
    cudaGetSymbolAddress((void**)&X2h,  g_X2h);
    cudaGetSymbolAddress((void**)&Gh,   g_Gh);
    cudaGetSymbolAddress((void**)&QKVh, g_QKVh);
    cudaGetSymbolAddress((void**)&B2h,  g_B2h);
    cudaGetSymbolAddress((void**)&Fh,   g_Fh);
    cudaGetSymbolAddress((void**)&WTh,  g_WTh);

    cudaFuncSetAttribute((const void*)k_gemm_mma<0, true>, cudaFuncAttributeMaxDynamicSharedMemorySize, SMEM_GEMM);
    cudaFuncSetAttribute((const void*)k_gemm_mma<2, true>, cudaFuncAttributeMaxDynamicSharedMemorySize, SMEM_GEMM);
    cudaFuncSetAttribute((const void*)k_gemm_qkv, cudaFuncAttributeMaxDynamicSharedMemorySize, SMEM_GEMM);
    cudaFuncSetAttribute((const void*)k_ffn,      cudaFuncAttributeMaxDynamicSharedMemorySize, SMEM_FFN);

    __half* WsT  = WTh;
    __half* WqT  = WTh + 16384;   // Wq|Wk|Wv contiguous
    __half* WoT  = WTh + 65536;
    __half* f1T  = WTh + 81920;   // 512 x 128
    __half* f2T  = WTh + 147456;  // 128 x 512

    const int GN4_BLOCKS = (4 * N_ * 32 + 255) / 256;  // 10000 (4 warps per node)

    // merged prep: weight cvt + x->fp16 + degree histogram
    cudaMemsetAsync(cnt, 0, N_ * sizeof(int));
    k_prep<<<PREP_END, 256>>>(Ws, Wq, Wk, Wv, Wo, f1w, f2w, WTh, x, Xh, ei, cnt);
    k_scan<<<1, 1024>>>(cnt, off, cur, inv);
    k_fill<<<(E_ + 255) / 256, 256>>>(ei, cur, srcs);

    // spatial GNN: gather-mean -> GEMM(Ws)+resid(x)+LN1 -> x1 fp16 (in-place Xh)
    k_gather_h<<<GN4_BLOCKS, 256>>>(Xh, off, srcs, inv, B1h);
    k_gemm_mma<2, true><<<dim3(1, 1250), 256, SMEM_GEMM>>>(B1h, WsT, bs, Xh, 128, x, g1, b1);

    // causal depthwise conv + LN2 (warp/node) -> X2h + Gh
    k_conv_ln<<<(N_ * 32 + 255) / 256, 256>>>(Xh, dk, g2, b2, spikes, X2h, Gh);

    // spike-gated message mean -> B1h
    k_gather_h<<<GN4_BLOCKS, 256>>>(Gh, off, srcs, inv, B1h);

    // fused Q/K/V projections (one launch, grid.x = 3)
    k_gemm_qkv<<<dim3(3, 1250), 256, SMEM_GEMM>>>(X2h, B1h, WqT, bq, bk, bv, QKVh);

    // windowed attention (attout reuses Xh, 2 nodes/block) -> Wo projection
    k_attn<<<N_ / 2, 256>>>(QKVh, QKVh + TNC_, QKVh + 2 * TNC_, tix, Xh);
    k_gemm_mma<0, true><<<dim3(1, 1250), 256, SMEM_GEMM>>>(Xh, WoT, bo, B2h, 128,
                                                           nullptr, nullptr, nullptr);

    // LIF scan + spike gate + channel mean (spike mean straight to d_out)
    float* outm = (out_size >= (int)(TNC_ + (long)TN_)) ? ((float*)d_out + TNC_) : spare;
    k_lif2<<<N_, 128>>>(B2h, Fh, outm);

    // fused FFN: gelu(fc1) -> fc2 + residual(x2 fp16) + LNf -> d_out
    k_ffn<<<1250, 256, SMEM_FFN>>>(Fh, f1T, f1b, f2T, f2b, X2h, gf, bf, (float*)d_out);
}

// round 17
// speedup vs baseline: 1.0160x; 1.0160x over previous
#include <cuda_runtime.h>
#include <cuda_fp16.h>
#include <math.h>
#include <stdint.h>

// Problem constants
#define T_   8
#define N_   20000
#define C_   128
#define E_   320000
#define H_   4
#define DH_  32
#define WIN_ 4
#define K_   5
#define CH_  512
#define TN_  (T_ * N_)
#define TNC_ ((long)T_ * N_ * C_)

// ---------------------------------------------------------------------------
// Scratch (__device__ globals; no cudaMalloc allowed)
// ---------------------------------------------------------------------------
__device__ float g_inv[N_];
__device__ int   g_cnt[N_];
__device__ int   g_off[N_ + 1];
__device__ int   g_cur[N_];
__device__ int   g_srcs[E_];
__device__ float g_spare[TN_];
__device__ __half g_Xh[T_ * N_ * C_];   // x fp16 -> x1 fp16 -> attout (staged reuse)
__device__ __half g_B1h[T_ * N_ * C_];  // gather outputs
__device__ __half g_X2h[T_ * N_ * C_];  // x2 fp16 (Q GEMM A + FFN resid)
__device__ __half g_Gh[T_ * N_ * C_];   // gated x2 (gather2 in)
__device__ __half g_QKVh[3 * T_ * N_ * C_];
__device__ __half g_B2h[T_ * N_ * C_];  // aggregated fp16 (feeds LIF)
__device__ __half g_Fh[T_ * N_ * C_];   // ffn_in fp16
// transposed fp16 weights: Ws,Wq,Wk,Wv,Wo (128x128), f1 (512x128), f2 (128x512)
__device__ __half g_WTh[5 * 128 * 128 + 512 * 128 + 128 * 512];

// ---------------------------------------------------------------------------
// Helpers
// ---------------------------------------------------------------------------
__device__ __forceinline__ uint32_t smem_u32(const void* p) {
    uint32_t a;
    asm("{ .reg .u64 t; cvta.to.shared.u64 t, %1; cvt.u32.u64 %0, t; }" : "=r"(a) : "l"(p));
    return a;
}
__device__ __forceinline__ float warp_sum(float v) {
#pragma unroll
    for (int o = 16; o; o >>= 1) v += __shfl_xor_sync(0xffffffffu, v, o);
    return v;
}
__device__ __forceinline__ float gelu_t(float v) {
    float t = 0.7978845608028654f * (v + 0.044715f * v * v * v);
    float th; asm("tanh.approx.f32 %0, %1;" : "=f"(th) : "f"(t));
    return 0.5f * v * (1.0f + th);
}
__device__ __forceinline__ void cp16(uint32_t dst, const void* src) {
    asm volatile("cp.async.cg.shared.global [%0], [%1], 16;" :: "r"(dst), "l"(src));
}
#define CP_COMMIT() asm volatile("cp.async.commit_group;" ::: "memory")
#define CP_WAIT0()  asm volatile("cp.async.wait_group 0;" ::: "memory")
#define CP_WAIT1()  asm volatile("cp.async.wait_group 1;" ::: "memory")

__device__ __forceinline__ void mma_f16(float* c, const uint32_t* a, uint32_t b0, uint32_t b1) {
    asm volatile("mma.sync.aligned.m16n8k16.row.col.f32.f16.f16.f32 "
                 "{%0,%1,%2,%3}, {%4,%5,%6,%7}, {%8,%9}, {%0,%1,%2,%3};"
                 : "+f"(c[0]), "+f"(c[1]), "+f"(c[2]), "+f"(c[3])
                 : "r"(a[0]), "r"(a[1]), "r"(a[2]), "r"(a[3]), "r"(b0), "r"(b1));
}
__device__ __forceinline__ uint32_t ldu32(const __half* p) {
    return *(const uint32_t*)p;
}

// ---------------------------------------------------------------------------
// Merged prep kernel: weight transposes + fp16 x copy + degree histogram.
// ---------------------------------------------------------------------------
__device__ __forceinline__ void tcvt_tile(const float* __restrict__ in,
                                          __half* __restrict__ out, int Kd, int Ncol,
                                          int bx, int by) {
    __shared__ float tile[32][33];
    int kb = by * 32, nb = bx * 32;
    int tx = threadIdx.x & 31, ty = threadIdx.x >> 5;
#pragma unroll
    for (int j = 0; j < 32; j += 8)
        tile[ty + j][tx] = in[(long)(kb + ty + j) * Ncol + nb + tx];
    __syncthreads();
#pragma unroll
    for (int j = 0; j < 32; j += 8) {
        float v = tile[tx][ty + j];
        out[(long)(nb + ty + j) * Kd + kb + tx] = __float2half(v);
    }
}

#define PREP_SQ   80
#define PREP_F1   (PREP_SQ + 64)
#define PREP_F2   (PREP_F1 + 64)
#define PREP_F2H  (PREP_F2 + 20000)
#define PREP_END  (PREP_F2H + 1250)

__global__ void k_prep(const float* w0, const float* w1, const float* w2,
                       const float* w3, const float* w4,
                       const float* f1w, const float* f2w,
                       __half* WTh,
                       const float* __restrict__ x, __half* __restrict__ xh,
                       const int* __restrict__ ei, int* __restrict__ cnt) {
    int b = blockIdx.x;
    if (b < PREP_SQ) {
        int w = b >> 4, tile = b & 15;
        const float* in;
        switch (w) {
            case 0: in = w0; break;
            case 1: in = w1; break;
            case 2: in = w2; break;
            case 3: in = w3; break;
            default: in = w4; break;
        }
        tcvt_tile(in, WTh + (long)w * 16384, 128, 128, tile & 3, tile >> 2);
    } else if (b < PREP_F1) {
        int t = b - PREP_SQ;
        tcvt_tile(f1w, WTh + 81920, 128, 512, t & 15, t >> 4);
    } else if (b < PREP_F2) {
        int t = b - PREP_F1;
        tcvt_tile(f2w, WTh + 147456, 512, 128, t & 3, t >> 2);
    } else if (b < PREP_F2H) {
        long i = ((long)(b - PREP_F2) * 256 + threadIdx.x) * 4;
        float4 v = *(const float4*)(x + i);
        __half2 h0 = __floats2half2_rn(v.x, v.y);
        __half2 h1 = __floats2half2_rn(v.z, v.w);
        uint2 u;
        u.x = *(uint32_t*)&h0;
        u.y = *(uint32_t*)&h1;
        *(uint2*)(xh + i) = u;
    } else {
        int e = (b - PREP_F2H) * 256 + threadIdx.x;
        if (e < E_) atomicAdd(&cnt[ei[E_ + e]], 1);
    }
}

// ---------------------------------------------------------------------------
// CSR scan + fill
// ---------------------------------------------------------------------------
__global__ void k_scan(const int* __restrict__ cnt, int* __restrict__ off,
                       int* __restrict__ cur, float* __restrict__ inv) {
    __shared__ int wsum[32];
    __shared__ int sbase;
    __shared__ int stot;
    if (threadIdx.x == 0) sbase = 0;
    __syncthreads();
    int lane = threadIdx.x & 31, w = threadIdx.x >> 5;
    for (int start = 0; start < N_; start += 1024) {
        int i = start + threadIdx.x;
        int v = (i < N_) ? cnt[i] : 0;
        int s = v;
#pragma unroll
        for (int o = 1; o < 32; o <<= 1) {
            int tmp = __shfl_up_sync(0xffffffffu, s, o);
            if (lane >= o) s += tmp;
        }
        if (lane == 31) wsum[w] = s;
        __syncthreads();
        if (w == 0) {
            int ws = wsum[lane];
#pragma unroll
            for (int o = 1; o < 32; o <<= 1) {
                int tmp = __shfl_up_sync(0xffffffffu, ws, o);
                if (lane >= o) ws += tmp;
            }
            wsum[lane] = ws;
            if (lane == 31) stot = ws;
        }
        __syncthreads();
        int incl = s + (w > 0 ? wsum[w - 1] : 0) + sbase;
        if (i < N_) {
            int excl = incl - v;
            off[i] = excl;
            cur[i] = excl;
            inv[i] = 1.0f / fmaxf((float)v, 1.0f);
        }
        __syncthreads();
        if (threadIdx.x == 0) sbase += stot;
        __syncthreads();
    }
    if (threadIdx.x == 0) off[N_] = sbase;
}

__global__ void k_fill(const int* __restrict__ ei, int* __restrict__ cur,
                       int* __restrict__ srcs) {
    int e = blockIdx.x * blockDim.x + threadIdx.x;
    if (e >= E_) return;
    int d = ei[E_ + e];
    int idx = atomicAdd(&cur[d], 1);
    srcs[idx] = ei[e];
}

// ---------------------------------------------------------------------------
// fp16 gather-mean, 2 warps per node (one per T-half), LDG.128, 2-edge unroll.
// fp16 pairwise add (__hadd2) per edge pair before fp32 accumulate:
// cuts conversion+FADD work ~33%.
// ---------------------------------------------------------------------------
__global__ void k_gather_h(const __half* __restrict__ xin, const int* __restrict__ off,
                           const int* __restrict__ srcs, const float* __restrict__ inv,
                           __half* __restrict__ out) {
    int gw = (int)((blockIdx.x * blockDim.x + threadIdx.x) >> 5);
    int lane = threadIdx.x & 31;
    if (gw >= 2 * N_) return;
    int n  = gw >> 1;
    int hh = gw & 1;                 // timestep half: t in [hh*4, hh*4+4)
    const int p = lane >> 4;         // parity within half
    const int c = lane & 15;         // 16B chunk (8 halfs)
    int s0 = off[n], s1 = off[n + 1];
    float acc[2][8];                 // 2 timesteps (hh*4 + 2i + p) x 8 channels
#pragma unroll
    for (int i = 0; i < 2; i++)
#pragma unroll
        for (int q = 0; q < 8; q++) acc[i][q] = 0.0f;

    const __half* xb = xin + c * 8 + (long)(hh * 4 + p) * N_ * C_;
    const long strideT2 = (long)2 * N_ * C_;

    int j = s0;
    for (; j + 1 < s1; j += 2) {
        int sA = srcs[j];
        int sB = srcs[j + 1];
        const __half* rA = xb + (long)sA * C_;
        const __half* rB = xb + (long)sB * C_;
        uint4 uA[2], uB[2];
#pragma unroll
        for (int i = 0; i < 2; i++) {
            uA[i] = *(const uint4*)(rA + i * strideT2);
            uB[i] = *(const uint4*)(rB + i * strideT2);
        }
#pragma unroll
        for (int i = 0; i < 2; i++) {
            const __half2* ha = (const __half2*)&uA[i];
            const __half2* hb = (const __half2*)&uB[i];
#pragma unroll
            for (int q = 0; q < 4; q++) {
                __half2 hs = __hadd2(ha[q], hb[q]);
                float2 f = __half22float2(hs);
                acc[i][2 * q + 0] += f.x;
                acc[i][2 * q + 1] += f.y;
            }
        }
    }
    if (j < s1) {
        int s = srcs[j];
        const __half* rp = xb + (long)s * C_;
        uint4 u[2];
#pragma unroll
        for (int i = 0; i < 2; i++)
            u[i] = *(const uint4*)(rp + i * strideT2);
#pragma unroll
        for (int i = 0; i < 2; i++) {
            const __half2* hu = (const __half2*)&u[i];
#pragma unroll
            for (int q = 0; q < 4; q++) {
                float2 f = __half22float2(hu[q]);
                acc[i][2 * q + 0] += f.x;
                acc[i][2 * q + 1] += f.y;
            }
        }
    }
    float iv = inv[n];
#pragma unroll
    for (int i = 0; i < 2; i++) {
        __half2 o[4];
#pragma unroll
        for (int q = 0; q < 4; q++)
            o[q] = __floats2half2_rn(acc[i][2 * q + 0] * iv, acc[i][2 * q + 1] * iv);
        *(uint4*)(out + ((long)(hh * 4 + 2 * i + p) * N_ + n) * C_ + c * 8) = *(uint4*)o;
    }
}

// ---------------------------------------------------------------------------
// GEMM core macros (pipelined, BK=32, 2-stage)
// ---------------------------------------------------------------------------
#define LDA_  40
#define SA0   0
#define SA1   10240
#define SB0   20480
#define SB1   30720
#define SBIAS 40960
#define SG    41472
#define SBB   41984
#define SRED  42496
#define SMEM_GEMM (SRED + 2048)

// ---------------------------------------------------------------------------
// fp16 mma.sync GEMM: Out = epilogue( (A @ BT^T) + bias )
// EPI 0: bias; EPI 2: bias + fp32 residual + LayerNorm. OUTH: half output.
// ---------------------------------------------------------------------------
template <int EPI, bool OUTH>
__global__ __launch_bounds__(256)
void k_gemm_mma(const __half* __restrict__ A, const __half* __restrict__ BT,
                const float* __restrict__ bias, void* __restrict__ OutV,
                int Kd,
                const float* __restrict__ resid,
                const float* __restrict__ lng, const float* __restrict__ lnb) {
    extern __shared__ char smem[];
    uint32_t sbase = smem_u32(smem);
    const int tid = threadIdx.x;
    const int wid = tid >> 5, lane = tid & 31;
    const int g = lane >> 2, t = lane & 3;
    const int warp_m = wid & 3, warp_n = wid >> 2;
    const long m0 = (long)blockIdx.y * 128;

    float* sbias = (float*)(smem + SBIAS);
    float* sg    = (float*)(smem + SG);
    float* sbb   = (float*)(smem + SBB);
    float* sred1 = (float*)(smem + SRED);
    float* sred2 = (float*)(smem + SRED + 1024);

    if (tid < 128) {
        sbias[tid] = bias[tid];
        if (EPI == 2) { sg[tid] = lng[tid]; sbb[tid] = lnb[tid]; }
    }

    float c[2][8][4];
#pragma unroll
    for (int mt = 0; mt < 2; mt++)
#pragma unroll
        for (int nt = 0; nt < 8; nt++)
#pragma unroll
            for (int j = 0; j < 4; j++) c[mt][nt][j] = 0.0f;

    const int nck = Kd >> 5;
    const int srow = tid >> 2;
    const int sseg = (tid & 3) * 8;
    {
        uint32_t sa = sbase + SA0, sb = sbase + SB0;
#pragma unroll
        for (int i = 0; i < 2; i++) {
            int r = srow + 64 * i;
            cp16(sa + (uint32_t)(r * LDA_ + sseg) * 2, A  + (m0 + r) * Kd + sseg);
            cp16(sb + (uint32_t)(r * LDA_ + sseg) * 2, BT + (long)r * Kd + sseg);
        }
        CP_COMMIT();
    }

    for (int ck = 0; ck < nck; ck++) {
        if (ck + 1 < nck) {
            int buf = (ck + 1) & 1;
            uint32_t sa = sbase + (buf ? SA1 : SA0);
            uint32_t sb = sbase + (buf ? SB1 : SB0);
            long kb = (long)(ck + 1) * 32;
#pragma unroll
            for (int i = 0; i < 2; i++) {
                int r = srow + 64 * i;
                cp16(sa + (uint32_t)(r * LDA_ + sseg) * 2, A  + (m0 + r) * Kd + kb + sseg);
                cp16(sb + (uint32_t)(r * LDA_ + sseg) * 2, BT + (long)r * Kd + kb + sseg);
            }
            CP_COMMIT();
            CP_WAIT1();
        } else {
            CP_WAIT0();
        }
        __syncthreads();

        const __half* As = (const __half*)(smem + ((ck & 1) ? SA1 : SA0));
        const __half* Bs = (const __half*)(smem + ((ck & 1) ? SB1 : SB0));
#pragma unroll
        for (int ks = 0; ks < 2; ks++) {
            int k0 = ks * 16 + 2 * t;
            uint32_t a[2][4];
#pragma unroll
            for (int mt = 0; mt < 2; mt++) {
                const __half* ap = As + (warp_m * 32 + mt * 16 + g) * LDA_ + k0;
                a[mt][0] = ldu32(ap);
                a[mt][1] = ldu32(ap + 8 * LDA_);
                a[mt][2] = ldu32(ap + 8);
                a[mt][3] = ldu32(ap + 8 * LDA_ + 8);
            }
#pragma unroll
            for (int nt = 0; nt < 8; nt++) {
                const __half* bp = Bs + (warp_n * 64 + nt * 8 + g) * LDA_ + k0;
                uint32_t b0 = ldu32(bp);
                uint32_t b1 = ldu32(bp + 8);
#pragma unroll
                for (int mt = 0; mt < 2; mt++) mma_f16(c[mt][nt], a[mt], b0, b1);
            }
        }
        __syncthreads();
    }

    if (EPI == 2) {
#pragma unroll
        for (int mt = 0; mt < 2; mt++) {
#pragma unroll
            for (int h = 0; h < 2; h++) {
                int rib = warp_m * 32 + mt * 16 + h * 8 + g;
                long gr = m0 + rib;
                float s1 = 0.f, s2 = 0.f;
#pragma unroll
                for (int nt = 0; nt < 8; nt++) {
                    int col = warp_n * 64 + nt * 8 + 2 * t;
                    float2 rv = *(const float2*)(resid + gr * 128 + col);
                    float v0 = c[mt][nt][h * 2 + 0] + sbias[col]     + rv.x;
                    float v1 = c[mt][nt][h * 2 + 1] + sbias[col + 1] + rv.y;
                    c[mt][nt][h * 2 + 0] = v0;
                    c[mt][nt][h * 2 + 1] = v1;
                    s1 += v0 + v1;
                    s2 += v0 * v0 + v1 * v1;
                }
                s1 += __shfl_xor_sync(0xffffffffu, s1, 1);
                s1 += __shfl_xor_sync(0xffffffffu, s1, 2);
                s2 += __shfl_xor_sync(0xffffffffu, s2, 1);
                s2 += __shfl_xor_sync(0xffffffffu, s2, 2);
                if (t == 0) {
                    sred1[rib * 2 + warp_n] = s1;
                    sred2[rib * 2 + warp_n] = s2;
                }
            }
        }
        __syncthreads();
#pragma unroll
        for (int mt = 0; mt < 2; mt++) {
#pragma unroll
            for (int h = 0; h < 2; h++) {
                int rib = warp_m * 32 + mt * 16 + h * 8 + g;
                long gr = m0 + rib;
                float s1 = sred1[rib * 2] + sred1[rib * 2 + 1];
                float s2 = sred2[rib * 2] + sred2[rib * 2 + 1];
                float mu = s1 * (1.0f / 128.0f);
                float var = s2 * (1.0f / 128.0f) - mu * mu;
                float rs = rsqrtf(var + 1e-5f);
#pragma unroll
                for (int nt = 0; nt < 8; nt++) {
                    int col = warp_n * 64 + nt * 8 + 2 * t;
                    float o0 = (c[mt][nt][h * 2 + 0] - mu) * rs * sg[col]     + sbb[col];
                    float o1 = (c[mt][nt][h * 2 + 1] - mu) * rs * sg[col + 1] + sbb[col + 1];
                    if (OUTH) {
                        *(__half2*)((__half*)OutV + gr * 128 + col) = __floats2half2_rn(o0, o1);
                    } else {
                        *(float2*)((float*)OutV + gr * 128 + col) = make_float2(o0, o1);
                    }
                }
            }
        }
    } else {
#pragma unroll
        for (int mt = 0; mt < 2; mt++) {
#pragma unroll
            for (int h = 0; h < 2; h++) {
                long gr = m0 + warp_m * 32 + mt * 16 + h * 8 + g;
#pragma unroll
                for (int nt = 0; nt < 8; nt++) {
                    int col = warp_n * 64 + nt * 8 + 2 * t;
                    float v0 = c[mt][nt][h * 2 + 0] + sbias[col];
                    float v1 = c[mt][nt][h * 2 + 1] + sbias[col + 1];
                    if (OUTH) {
                        *(__half2*)((__half*)OutV + gr * 128 + col) = __floats2half2_rn(v0, v1);
                    } else {
                        *(float2*)((float*)OutV + gr * 128 + col) = make_float2(v0, v1);
                    }
                }
            }
        }
    }
}

// ---------------------------------------------------------------------------
// Fused QKV GEMM (pipelined): grid (3, 1250).
// ---------------------------------------------------------------------------
__global__ __launch_bounds__(256)
void k_gemm_qkv(const __half* __restrict__ Aq, const __half* __restrict__ Akv,
                const __half* __restrict__ WQKV,
                const float* __restrict__ bq, const float* __restrict__ bk,
                const float* __restrict__ bv, __half* __restrict__ QKV) {
    extern __shared__ char smem[];
    uint32_t sbase = smem_u32(smem);
    const int tid = threadIdx.x;
    const int wid = tid >> 5, lane = tid & 31;
    const int g = lane >> 2, t = lane & 3;
    const int warp_m = wid & 3, warp_n = wid >> 2;
    const long m0 = (long)blockIdx.y * 128;
    const int sel = blockIdx.x;

    const __half* A  = (sel == 0) ? Aq : Akv;
    const __half* BT = WQKV + (long)sel * 16384;
    const float* biasp = (sel == 0) ? bq : ((sel == 1) ? bk : bv);
    __half* Out = QKV + (long)sel * TNC_;

    float* sbias = (float*)(smem + SBIAS);
    if (tid < 128) sbias[tid] = biasp[tid];

    float c[2][8][4];
#pragma unroll
    for (int mt = 0; mt < 2; mt++)
#pragma unroll
        for (int nt = 0; nt < 8; nt++)
#pragma unroll
            for (int j = 0; j < 4; j++) c[mt][nt][j] = 0.0f;

    const int srow = tid >> 2;
    const int sseg = (tid & 3) * 8;
    {
        uint32_t sa = sbase + SA0, sb = sbase + SB0;
#pragma unroll
        for (int i = 0; i < 2; i++) {
            int r = srow + 64 * i;
            cp16(sa + (uint32_t)(r * LDA_ + sseg) * 2, A  + (m0 + r) * 128 + sseg);
            cp16(sb + (uint32_t)(r * LDA_ + sseg) * 2, BT + (long)r * 128 + sseg);
        }
        CP_COMMIT();
    }

#pragma unroll
    for (int ck = 0; ck < 4; ck++) {
        if (ck + 1 < 4) {
            int buf = (ck + 1) & 1;
            uint32_t sa = sbase + (buf ? SA1 : SA0);
            uint32_t sb = sbase + (buf ? SB1 : SB0);
            long kb = (long)(ck + 1) * 32;
#pragma unroll
            for (int i = 0; i < 2; i++) {
                int r = srow + 64 * i;
                cp16(sa + (uint32_t)(r * LDA_ + sseg) * 2, A  + (m0 + r) * 128 + kb + sseg);
                cp16(sb + (uint32_t)(r * LDA_ + sseg) * 2, BT + (long)r * 128 + kb + sseg);
            }
            CP_COMMIT();
            CP_WAIT1();
        } else {
            CP_WAIT0();
        }
        __syncthreads();

        const __half* As = (const __half*)(smem + ((ck & 1) ? SA1 : SA0));
        const __half* Bs = (const __half*)(smem + ((ck & 1) ? SB1 : SB0));
#pragma unroll
        for (int ks = 0; ks < 2; ks++) {
            int k0 = ks * 16 + 2 * t;
            uint32_t a[2][4];
#pragma unroll
            for (int mt = 0; mt < 2; mt++) {
                const __half* ap = As + (warp_m * 32 + mt * 16 + g) * LDA_ + k0;
                a[mt][0] = ldu32(ap);
                a[mt][1] = ldu32(ap + 8 * LDA_);
                a[mt][2] = ldu32(ap + 8);
                a[mt][3] = ldu32(ap + 8 * LDA_ + 8);
            }
#pragma unroll
            for (int nt = 0; nt < 8; nt++) {
                const __half* bp = Bs + (warp_n * 64 + nt * 8 + g) * LDA_ + k0;
                uint32_t b0 = ldu32(bp);
                uint32_t b1 = ldu32(bp + 8);
#pragma unroll
                for (int mt = 0; mt < 2; mt++) mma_f16(c[mt][nt], a[mt], b0, b1);
            }
        }
        __syncthreads();
    }

#pragma unroll
    for (int mt = 0; mt < 2; mt++) {
#pragma unroll
        for (int h = 0; h < 2; h++) {
            long gr = m0 + warp_m * 32 + mt * 16 + h * 8 + g;
#pragma unroll
            for (int nt = 0; nt < 8; nt++) {
                int col = warp_n * 64 + nt * 8 + 2 * t;
                float v0 = c[mt][nt][h * 2 + 0] + sbias[col];
                float v1 = c[mt][nt][h * 2 + 1] + sbias[col + 1];
                *(__half2*)(Out + gr * 128 + col) = __floats2half2_rn(v0, v1);
            }
        }
    }
}

// ---------------------------------------------------------------------------
// Fused FFN (fp16 operands): Out = LN( resid(fp16) + fc2(gelu(fc1(A))) )
// ---------------------------------------------------------------------------
#define FFS   136
#define FFTB  (128 * FFS * 2)
#define FFA   0
#define FFH   FFTB
#define FFW   (2 * FFTB)
#define FFBO  (3 * FFTB)
#define FFG   (FFBO + 512)
#define FFBB  (FFG + 512)
#define FFR1  (FFBB + 512)
#define FFR2  (FFR1 + 1024)
#define SMEM_FFN (FFR2 + 1024)

__global__ __launch_bounds__(256)
void k_ffn(const __half* __restrict__ A, const __half* __restrict__ F1T,
           const float* __restrict__ f1b, const __half* __restrict__ F2T,
           const float* __restrict__ f2b, const __half* __restrict__ residh,
           const float* __restrict__ lng, const float* __restrict__ lnb,
           float* __restrict__ Out) {
    extern __shared__ char smem[];
    uint32_t sbase = smem_u32(smem);
    __half* SA = (__half*)(smem + FFA);
    __half* SH = (__half*)(smem + FFH);
    __half* SW = (__half*)(smem + FFW);
    float* sbo = (float*)(smem + FFBO);
    float* sg  = (float*)(smem + FFG);
    float* sbb = (float*)(smem + FFBB);
    float* sred1 = (float*)(smem + FFR1);
    float* sred2 = (float*)(smem + FFR2);
    const int tid = threadIdx.x;
    const int wid = tid >> 5, lane = tid & 31;
    const int g = lane >> 2, t4 = lane & 3;
    const int wm = wid & 3, wn = wid >> 2;
    const long m0 = (long)blockIdx.x * 128;

    if (tid < 128) { sbo[tid] = f2b[tid]; sg[tid] = lng[tid]; sbb[tid] = lnb[tid]; }

    const int arow = tid >> 4;
    const int aseg = (tid & 15) * 8;
#pragma unroll
    for (int i = 0; i < 8; i++) {
        int r = arow + 16 * i;
        cp16(sbase + FFA + (uint32_t)(r * FFS + aseg) * 2, A + (m0 + r) * 128 + aseg);
    }
    CP_COMMIT();

    float oacc[2][8][4];
#pragma unroll
    for (int mt = 0; mt < 2; mt++)
#pragma unroll
        for (int nt = 0; nt < 8; nt++)
#pragma unroll
            for (int j = 0; j < 4; j++) oacc[mt][nt][j] = 0.0f;

    for (int ch = 0; ch < 4; ch++) {
#pragma unroll
        for (int i = 0; i < 8; i++) {
            int r = arow + 16 * i;
            cp16(sbase + FFW + (uint32_t)(r * FFS + aseg) * 2,
                 F1T + (long)(ch * 128 + r) * 128 + aseg);
        }
        CP_COMMIT();
        CP_WAIT0();
        __syncthreads();

        float hacc[2][8][4];
#pragma unroll
        for (int mt = 0; mt < 2; mt++)
#pragma unroll
            for (int nt = 0; nt < 8; nt++)
#pragma unroll
                for (int j = 0; j < 4; j++) hacc[mt][nt][j] = 0.0f;
#pragma unroll
        for (int ks = 0; ks < 8; ks++) {
            int k0 = ks * 16 + 2 * t4;
            uint32_t a[2][4];
#pragma unroll
            for (int mt = 0; mt < 2; mt++) {
                const __half* ap = SA + (wm * 32 + mt * 16 + g) * FFS + k0;
                a[mt][0] = ldu32(ap);
                a[mt][1] = ldu32(ap + 8 * FFS);
                a[mt][2] = ldu32(ap + 8);
                a[mt][3] = ldu32(ap + 8 * FFS + 8);
            }
#pragma unroll
            for (int nt = 0; nt < 8; nt++) {
                const __half* bp = SW + (wn * 64 + nt * 8 + g) * FFS + k0;
                uint32_t b0 = ldu32(bp);
                uint32_t b1 = ldu32(bp + 8);
#pragma unroll
                for (int mt = 0; mt < 2; mt++) mma_f16(hacc[mt][nt], a[mt], b0, b1);
            }
        }
        __syncthreads();

#pragma unroll
        for (int i = 0; i < 8; i++) {
            int r = arow + 16 * i;
            cp16(sbase + FFW + (uint32_t)(r * FFS + aseg) * 2,
                 F2T + (long)r * 512 + ch * 128 + aseg);
        }
        CP_COMMIT();

#pragma unroll
        for (int mt = 0; mt < 2; mt++) {
#pragma unroll
            for (int h = 0; h < 2; h++) {
                int row = wm * 32 + mt * 16 + h * 8 + g;
#pragma unroll
                for (int nt = 0; nt < 8; nt++) {
                    int col = wn * 64 + nt * 8 + 2 * t4;
                    float b0 = f1b[ch * 128 + col];
                    float b1 = f1b[ch * 128 + col + 1];
                    float h0 = gelu_t(hacc[mt][nt][h * 2 + 0] + b0);
                    float h1 = gelu_t(hacc[mt][nt][h * 2 + 1] + b1);
                    *(__half2*)(SH + row * FFS + col) = __floats2half2_rn(h0, h1);
                }
            }
        }
        CP_WAIT0();
        __syncthreads();

#pragma unroll
        for (int ks = 0; ks < 8; ks++) {
            int k0 = ks * 16 + 2 * t4;
            uint32_t a[2][4];
#pragma unroll
            for (int mt = 0; mt < 2; mt++) {
                const __half* ap = SH + (wm * 32 + mt * 16 + g) * FFS + k0;
                a[mt][0] = ldu32(ap);
                a[mt][1] = ldu32(ap + 8 * FFS);
                a[mt][2] = ldu32(ap + 8);
                a[mt][3] = ldu32(ap + 8 * FFS + 8);
            }
#pragma unroll
            for (int nt = 0; nt < 8; nt++) {
                const __half* bp = SW + (wn * 64 + nt * 8 + g) * FFS + k0;
                uint32_t b0 = ldu32(bp);
                uint32_t b1 = ldu32(bp + 8);
#pragma unroll
                for (int mt = 0; mt < 2; mt++) mma_f16(oacc[mt][nt], a[mt], b0, b1);
            }
        }
        __syncthreads();
    }

#pragma unroll
    for (int mt = 0; mt < 2; mt++) {
#pragma unroll
        for (int h = 0; h < 2; h++) {
            int rib = wm * 32 + mt * 16 + h * 8 + g;
            long gr = m0 + rib;
            float s1 = 0.f, s2 = 0.f;
#pragma unroll
            for (int nt = 0; nt < 8; nt++) {
                int col = wn * 64 + nt * 8 + 2 * t4;
                float2 rv = __half22float2(*(const __half2*)(residh + gr * 128 + col));
                float v0 = oacc[mt][nt][h * 2 + 0] + sbo[col]     + rv.x;
                float v1 = oacc[mt][nt][h * 2 + 1] + sbo[col + 1] + rv.y;
                oacc[mt][nt][h * 2 + 0] = v0;
                oacc[mt][nt][h * 2 + 1] = v1;
                s1 += v0 + v1;
                s2 += v0 * v0 + v1 * v1;
            }
            s1 += __shfl_xor_sync(0xffffffffu, s1, 1);
            s1 += __shfl_xor_sync(0xffffffffu, s1, 2);
            s2 += __shfl_xor_sync(0xffffffffu, s2, 1);
            s2 += __shfl_xor_sync(0xffffffffu, s2, 2);
            if (t4 == 0) {
                sred1[rib * 2 + wn] = s1;
                sred2[rib * 2 + wn] = s2;
            }
        }
    }
    __syncthreads();
#pragma unroll
    for (int mt = 0; mt < 2; mt++) {
#pragma unroll
        for (int h = 0; h < 2; h++) {
            int rib = wm * 32 + mt * 16 + h * 8 + g;
            long gr = m0 + rib;
            float s1 = sred1[rib * 2] + sred1[rib * 2 + 1];
            float s2 = sred2[rib * 2] + sred2[rib * 2 + 1];
            float mu = s1 * (1.0f / 128.0f);
            float var = s2 * (1.0f / 128.0f) - mu * mu;
            float rs = rsqrtf(var + 1e-5f);
#pragma unroll
            for (int nt = 0; nt < 8; nt++) {
                int col = wn * 64 + nt * 8 + 2 * t4;
                float o0 = (oacc[mt][nt][h * 2 + 0] - mu) * rs * sg[col]     + sbb[col];
                float o1 = (oacc[mt][nt][h * 2 + 1] - mu) * rs * sg[col + 1] + sbb[col + 1];
                *(float2*)(Out + gr * 128 + col) = make_float2(o0, o1);
            }
        }
    }
}

// ---------------------------------------------------------------------------
// x2 = LN(x1 + causal depthwise conv over time): warp-per-node, shuffle LN.
// ---------------------------------------------------------------------------
__global__ void k_conv_ln(const __half* __restrict__ x1h, const float* __restrict__ dk,
                          const float* __restrict__ g, const float* __restrict__ be,
                          const float* __restrict__ spikes,
                          __half* __restrict__ outh, __half* __restrict__ gh) {
    int n = (int)((blockIdx.x * blockDim.x + threadIdx.x) >> 5);
    int lane = threadIdx.x & 31;
    if (n >= N_) return;
    int c0 = lane * 4;
    float xs[T_][4];
#pragma unroll
    for (int t = 0; t < T_; t++) {
        uint2 u = *(const uint2*)(x1h + ((long)t * N_ + n) * C_ + c0);
        float2 f0 = __half22float2(*reinterpret_cast<__half2*>(&u.x));
        float2 f1 = __half22float2(*reinterpret_cast<__half2*>(&u.y));
        xs[t][0] = f0.x; xs[t][1] = f0.y; xs[t][2] = f1.x; xs[t][3] = f1.y;
    }
    float w[4][K_];
#pragma unroll
    for (int q = 0; q < 4; q++)
#pragma unroll
        for (int j = 0; j < K_; j++) w[q][j] = dk[(c0 + q) * K_ + j];
    float gc[4], bc[4];
#pragma unroll
    for (int q = 0; q < 4; q++) { gc[q] = g[c0 + q]; bc[q] = be[c0 + q]; }

#pragma unroll
    for (int t = 0; t < T_; t++) {
        float v[4];
#pragma unroll
        for (int q = 0; q < 4; q++) {
            float acc = xs[t][q];
#pragma unroll
            for (int j = 0; j < K_; j++)
                if (t - j >= 0) acc += w[q][j] * xs[t - j][q];
            v[q] = acc;
        }
        float l1 = v[0] + v[1] + v[2] + v[3];
        float l2 = v[0] * v[0] + v[1] * v[1] + v[2] * v[2] + v[3] * v[3];
        float s1 = warp_sum(l1);
        float s2 = warp_sum(l2);
        float mu = s1 * (1.0f / 128.0f);
        float var = s2 * (1.0f / 128.0f) - mu * mu;
        float rs = rsqrtf(var + 1e-5f);
        float spk = spikes[(long)t * N_ + n];
        float o[4];
#pragma unroll
        for (int q = 0; q < 4; q++) o[q] = (v[q] - mu) * rs * gc[q] + bc[q];
        __half2 h0 = __floats2half2_rn(o[0], o[1]);
        __half2 h1 = __floats2half2_rn(o[2], o[3]);
        uint2 uo;
        uo.x = *(uint32_t*)&h0;
        uo.y = *(uint32_t*)&h1;
        *(uint2*)(outh + ((long)t * N_ + n) * C_ + c0) = uo;
        __half2 g0 = __floats2half2_rn(o[0] * spk, o[1] * spk);
        __half2 g1 = __floats2half2_rn(o[2] * spk, o[3] * spk);
        uint2 ug;
        ug.x = *(uint32_t*)&g0;
        ug.y = *(uint32_t*)&g1;
        *(uint2*)(gh + ((long)t * N_ + n) * C_ + c0) = ug;
    }
}

// ---------------------------------------------------------------------------
// Windowed attention (fp16 I/O): 2 nodes per block, 8 warps (4 heads x 2).
// ---------------------------------------------------------------------------
__global__ void k_attn(const __half* __restrict__ q, const __half* __restrict__ k,
                       const __half* __restrict__ v, const int* __restrict__ tix,
                       __half* __restrict__ out) {
    int n = blockIdx.x * 2 + (threadIdx.x >> 7);
    int h = (threadIdx.x >> 5) & 3, d = threadIdx.x & 31;
    long base0 = (long)n * C_ + h * DH_ + d;
    float qv[T_], kv[T_], vv[T_];
    int ti[T_];
#pragma unroll
    for (int t = 0; t < T_; t++) {
        long idx = base0 + (long)t * N_ * C_;
        qv[t] = __half2float(q[idx]);
        kv[t] = __half2float(k[idx]);
        vv[t] = __half2float(v[idx]);
        ti[t] = tix[t];
    }
#pragma unroll
    for (int t = 0; t < T_; t++) {
        float sc[WIN_];
#pragma unroll
        for (int w = 0; w < WIN_; w++) {
            int tp = t - w; if (tp < 0) tp = 0;
            bool ok = (t >= w) && ((ti[t] - ti[tp]) < WIN_);
            float pr = (t >= w) ? qv[t] * kv[tp] : 0.0f;
            float dot = warp_sum(pr) * 0.17677669529663687f;
            sc[w] = ok ? dot : -1e9f;
        }
        float mx = sc[0];
#pragma unroll
        for (int w = 1; w < WIN_; w++) mx = fmaxf(mx, sc[w]);
        float den = 0.0f, ex[WIN_];
#pragma unroll
        for (int w = 0; w < WIN_; w++) { ex[w] = expf(sc[w] - mx); den += ex[w]; }
        float o = 0.0f;
#pragma unroll
        for (int w = 0; w < WIN_; w++)
            if (t - w >= 0) o += ex[w] * vv[t - w];
        out[base0 + (long)t * N_ * C_] = __float2half(o / den);
    }
}

// ---------------------------------------------------------------------------
// LIF scan + spike gate + channel-mean, block-per-node, ballot count.
// ---------------------------------------------------------------------------
__global__ void k_lif2(const __half* __restrict__ agg, __half* __restrict__ ffn_in,
                       float* __restrict__ outm) {
    int n = blockIdx.x;
    int c = threadIdx.x;
    int lane = c & 31, wi = c >> 5;
    __shared__ float red[T_][4];
    float a[T_];
#pragma unroll
    for (int t = 0; t < T_; t++)
        a[t] = __half2float(agg[((long)t * N_ + n) * C_ + c]);
    float vm = 0.0f;
#pragma unroll
    for (int t = 0; t < T_; t++) {
        float vn = 0.95f * vm + a[t];
        bool spk = (vn >= 1.0f);
        float s = spk ? 1.0f : 0.0f;
        vm = vn * (1.0f - s);
        ffn_in[((long)t * N_ + n) * C_ + c] = __float2half(a[t] * s);
        uint32_t bal = __ballot_sync(0xffffffffu, spk);
        if (lane == 0) red[t][wi] = (float)__popc(bal);
    }
    __syncthreads();
    if (c < T_)
        outm[(long)c * N_ + n] = (red[c][0] + red[c][1] + red[c][2] + red[c][3]) * (1.0f / 128.0f);
}

// ---------------------------------------------------------------------------
// Launch
// ---------------------------------------------------------------------------
extern "C" void kernel_launch(void* const* d_in, const int* in_sizes, int n_in,
                              void* d_out, int out_size) {
    const float* x      = (const float*)d_in[0];
    const float* spikes = (const float*)d_in[1];
    const int*   ei     = (const int*)d_in[2];
    const int*   tix    = (const int*)d_in[3];
    const float* Ws  = (const float*)d_in[4];
    const float* bs  = (const float*)d_in[5];
    const float* dk  = (const float*)d_in[6];
    const float* g1  = (const float*)d_in[7];
    const float* b1  = (const float*)d_in[8];
    const float* g2  = (const float*)d_in[9];
    const float* b2  = (const float*)d_in[10];
    const float* gf  = (const float*)d_in[11];
    const float* bf  = (const float*)d_in[12];
    const float* Wq  = (const float*)d_in[13];
    const float* bq  = (const float*)d_in[14];
    const float* Wk  = (const float*)d_in[15];
    const float* bk  = (const float*)d_in[16];
    const float* Wv  = (const float*)d_in[17];
    const float* bv  = (const float*)d_in[18];
    const float* Wo  = (const float*)d_in[19];
    const float* bo  = (const float*)d_in[20];
    const float* f1w = (const float*)d_in[21];
    const float* f1b = (const float*)d_in[22];
    const float* f2w = (const float*)d_in[23];
    const float* f2b = (const float*)d_in[24];

    float *inv, *spare;
    __half *Xh, *B1h, *X2h, *Gh, *QKVh, *B2h, *Fh, *WTh;
    int *cnt, *off, *cur, *srcs;
    cudaGetSymbolAddress((void**)&inv,  g_inv);
    cudaGetSymbolAddress((void**)&cnt,  g_cnt);
    cudaGetSymbolAddress((void**)&off,  g_off);
    cudaGetSymbolAddress((void**)&cur,  g_cur);
    cudaGetSymbolAddress((void**)&srcs, g_srcs);
    cudaGetSymbolAddress((void**)&spare, g_spare);
    cudaGetSymbolAddress((void**)&Xh,   g_Xh);
    cudaGetSymbolAddress((void**)&B1h,  g_B1h);
    cudaGetSymbolAddress((void**)&X2h,  g_X2h);
    cudaGetSymbolAddress((void**)&Gh,   g_Gh);
    cudaGetSymbolAddress((void**)&QKVh, g_QKVh);
    cudaGetSymbolAddress((void**)&B2h,  g_B2h);
    cudaGetSymbolAddress((void**)&Fh,   g_Fh);
    cudaGetSymbolAddress((void**)&WTh,  g_WTh);

    cudaFuncSetAttribute((const void*)k_gemm_mma<0, true>, cudaFuncAttributeMaxDynamicSharedMemorySize, SMEM_GEMM);
    cudaFuncSetAttribute((const void*)k_gemm_mma<2, true>, cudaFuncAttributeMaxDynamicSharedMemorySize, SMEM_GEMM);
    cudaFuncSetAttribute((const void*)k_gemm_qkv, cudaFuncAttributeMaxDynamicSharedMemorySize, SMEM_GEMM);
    cudaFuncSetAttribute((const void*)k_ffn,      cudaFuncAttributeMaxDynamicSharedMemorySize, SMEM_FFN);

    __half* WsT  = WTh;
    __half* WqT  = WTh + 16384;   // Wq|Wk|Wv contiguous
    __half* WoT  = WTh + 65536;
    __half* f1T  = WTh + 81920;   // 512 x 128
    __half* f2T  = WTh + 147456;  // 128 x 512

    const int GN2_BLOCKS = (2 * N_ * 32 + 255) / 256;  // 5000 (2 warps per node)

    // merged prep: weight cvt + x->fp16 + degree histogram
    cudaMemsetAsync(cnt, 0, N_ * sizeof(int));
    k_prep<<<PREP_END, 256>>>(Ws, Wq, Wk, Wv, Wo, f1w, f2w, WTh, x, Xh, ei, cnt);
    k_scan<<<1, 1024>>>(cnt, off, cur, inv);
    k_fill<<<(E_ + 255) / 256, 256>>>(ei, cur, srcs);

    // spatial GNN: gather-mean -> GEMM(Ws)+resid(x)+LN1 -> x1 fp16 (in-place Xh)
    k_gather_h<<<GN2_BLOCKS, 256>>>(Xh, off, srcs, inv, B1h);
    k_gemm_mma<2, true><<<dim3(1, 1250), 256, SMEM_GEMM>>>(B1h, WsT, bs, Xh, 128, x, g1, b1);

    // causal depthwise conv + LN2 (warp/node) -> X2h + Gh
    k_conv_ln<<<(N_ * 32 + 255) / 256, 256>>>(Xh, dk, g2, b2, spikes, X2h, Gh);

    // spike-gated message mean -> B1h
    k_gather_h<<<GN2_BLOCKS, 256>>>(Gh, off, srcs, inv, B1h);

    // fused Q/K/V projections (one launch, grid.x = 3)
    k_gemm_qkv<<<dim3(3, 1250), 256, SMEM_GEMM>>>(X2h, B1h, WqT, bq, bk, bv, QKVh);

    // windowed attention (attout reuses Xh, 2 nodes/block) -> Wo projection
    k_attn<<<N_ / 2, 256>>>(QKVh, QKVh + TNC_, QKVh + 2 * TNC_, tix, Xh);
    k_gemm_mma<0, true><<<dim3(1, 1250), 256, SMEM_GEMM>>>(Xh, WoT, bo, B2h, 128,
                                                           nullptr, nullptr, nullptr);

    // LIF scan + spike gate + channel mean (spike mean straight to d_out)
    float* outm = (out_size >= (int)(TNC_ + (long)TN_)) ? ((float*)d_out + TNC_) : spare;
    k_lif2<<<N_, 128>>>(B2h, Fh, outm);

    // fused FFN: gelu(fc1) -> fc2 + residual(x2 fp16) + LNf -> d_out
    k_ffn<<<1250, 256, SMEM_FFN>>>(Fh, f1T, f1b, f2T, f2b, X2h, gf, bf, (float*)d_out);
}